// round 12
// baseline (speedup 1.0000x reference)
#include <cuda_runtime.h>
#include <float.h>

// Problem constants
#define B_   4
#define C_   64
#define T_   32
#define WH_  4096                  // W*H per frame
#define FRAME4_ (WH_ / 4)          // 1024 float4 per frame
#define PLANE4_ ((T_ * WH_) / 4)   // 32768 float4 per (b,c) plane
#define NBT_ (B_ * T_)             // 128 frames

#define K1_CHUNKS  4               // reduce blocks per frame
#define NTHREADS   256

#define HALF_FRAMES (2 * T_)               // 64 frames per batch-pair
#define NPROD_H  (K1_CHUNKS * HALF_FRAMES) // 256 reduce blocks per half
#define NCONS_H  (2 * C_ * 64)             // 8192 apply blocks per half

// Scratch (device globals — no allocation)
__device__ float g_e[(size_t)NBT_ * WH_];          // unnormalized exp(fusion), 2MB
__device__ float g_part[NBT_ * K1_CHUNKS];         // per-chunk exp-sums

__device__ __forceinline__ float sigmoidf_(float v) {
    return 1.0f / (1.0f + __expf(-v));
}

// ---- reduce work-item: (frame bt, chunk): channel mean/max + exp + partial sum ----
__device__ __forceinline__ void reduce_work(
    const float* __restrict__ x, const float* __restrict__ skin,
    int bt, int chunk, int tid)
{
    const int b  = bt >> 5;
    const int t  = bt & 31;
    const int p4 = chunk * NTHREADS + tid;           // 0..1023 within frame

    const size_t base4 = ((size_t)(b * C_ * T_) + t) * FRAME4_ + p4;
    const float4* __restrict__ x4 = (const float4*)x;

    float4 s = make_float4(0.f, 0.f, 0.f, 0.f);
    float4 m = make_float4(-FLT_MAX, -FLT_MAX, -FLT_MAX, -FLT_MAX);

    #pragma unroll 8
    for (int c = 0; c < C_; c++) {
        const float4 v = x4[base4 + (size_t)c * PLANE4_];
        s.x += v.x; s.y += v.y; s.z += v.z; s.w += v.w;
        m.x = fmaxf(m.x, v.x); m.y = fmaxf(m.y, v.y);
        m.z = fmaxf(m.z, v.z); m.w = fmaxf(m.w, v.w);
    }

    const float4 k = __ldcs(&((const float4*)skin)[(size_t)bt * FRAME4_ + p4]);

    const float inv_c = 1.0f / (float)C_;
    float4 e;
    // fusion in (0,3): exp safe without max subtraction
    e.x = __expf(sigmoidf_(s.x * inv_c) + sigmoidf_(m.x) + k.x);
    e.y = __expf(sigmoidf_(s.y * inv_c) + sigmoidf_(m.y) + k.y);
    e.z = __expf(sigmoidf_(s.z * inv_c) + sigmoidf_(m.z) + k.z);
    e.w = __expf(sigmoidf_(s.w * inv_c) + sigmoidf_(m.w) + k.w);

    ((float4*)g_e)[(size_t)bt * FRAME4_ + p4] = e;

    float ls = e.x + e.y + e.z + e.w;
    #pragma unroll
    for (int o = 16; o; o >>= 1) ls += __shfl_xor_sync(0xffffffffu, ls, o);

    __shared__ float red[8];
    if ((tid & 31) == 0) red[tid >> 5] = ls;
    __syncthreads();
    if (tid == 0) {
        float v = red[0];
        #pragma unroll
        for (int w = 1; w < 8; w++) v += red[w];
        g_part[bt * K1_CHUNKS + chunk] = v;
    }
}

// ---- apply work-item: (plane, blk): out = x * e * inv_sum ----
__device__ __forceinline__ void apply_work(
    const float* __restrict__ x, float* __restrict__ out,
    float* __restrict__ attn, int plane, int blk, int tid)
{
    const int b  = plane >> 6;
    const int c  = plane & 63;
    const int i4 = blk * 512 + tid;
    const int t  = blk >> 1;                 // block-constant frame
    const int bt = b * T_ + t;

    const size_t px = (size_t)plane * PLANE4_ + i4;
    const size_t pa = (size_t)b * PLANE4_ + i4;

    const float4 xv0 = __ldcs(&((const float4*)x)[px]);
    const float4 xv1 = __ldcs(&((const float4*)x)[px + 256]);
    const float4 ev0 = __ldcs(&((const float4*)g_e)[pa]);
    const float4 ev1 = __ldcs(&((const float4*)g_e)[pa + 256]);

    const float* __restrict__ p = &g_part[bt * K1_CHUNKS];
    float tot = 0.f;
    #pragma unroll
    for (int r = 0; r < K1_CHUNKS; r++) tot += p[r];
    const float inv = __frcp_rn(tot);

    float4 a0, a1;
    a0.x = ev0.x * inv; a0.y = ev0.y * inv; a0.z = ev0.z * inv; a0.w = ev0.w * inv;
    a1.x = ev1.x * inv; a1.y = ev1.y * inv; a1.z = ev1.z * inv; a1.w = ev1.w * inv;

    float4 o0, o1;
    o0.x = xv0.x * a0.x; o0.y = xv0.y * a0.y; o0.z = xv0.z * a0.z; o0.w = xv0.w * a0.w;
    o1.x = xv1.x * a1.x; o1.y = xv1.y * a1.y; o1.z = xv1.z * a1.z; o1.w = xv1.w * a1.w;

    __stcs(&((float4*)out)[px],       o0);
    __stcs(&((float4*)out)[px + 256], o1);

    if (c == 0) {
        __stcs(&((float4*)attn)[pa],       a0);
        __stcs(&((float4*)attn)[pa + 256], a1);
    }
}

// ---------------- Launch 1: reduce batches 0,1 ----------------
__global__ __launch_bounds__(NTHREADS) void k_reduce_b01(
    const float* __restrict__ x, const float* __restrict__ skin)
{
    // grid (K1_CHUNKS, 64): bt = 0..63
    reduce_work(x, skin, blockIdx.y, blockIdx.x, threadIdx.x);
}

// ---------------- Launch 2 (mixed): reduce b23  ∪  apply b01 ----------------
// Producers first in grid (dispatch order); data of the two halves is disjoint,
// so no intra-kernel synchronization is needed.
__global__ __launch_bounds__(NTHREADS) void k_mixed(
    const float* __restrict__ x, const float* __restrict__ skin,
    float* __restrict__ out, float* __restrict__ attn)
{
    const int bid = blockIdx.x;
    const int tid = threadIdx.x;
    if (bid < NPROD_H) {
        // reduce for frames 64..127 (batches 2,3)
        const int chunk = bid & (K1_CHUNKS - 1);
        const int bt    = HALF_FRAMES + (bid >> 2);
        reduce_work(x, skin, bt, chunk, tid);
    } else {
        // apply for batches 0,1; reversed traversal to match launch-1 recency
        const int cid   = bid - NPROD_H;            // 0..8191
        const int plane = 127 - (cid >> 6);         // 127..0
        const int blk   = 63 - (cid & 63);          // 63..0
        apply_work(x, out, attn, plane, blk, tid);
    }
}

// ---------------- Launch 3: apply batches 2,3 ----------------
__global__ __launch_bounds__(NTHREADS) void k_apply_b23(
    const float* __restrict__ x, float* __restrict__ out, float* __restrict__ attn)
{
    // grid (64, 128); reversed within b23 to match launch-2 recency
    const int plane = 255 - blockIdx.y;             // 255..128
    const int blk   = 63 - blockIdx.x;              // 63..0
    apply_work(x, out, attn, plane, blk, threadIdx.x);
}

extern "C" void kernel_launch(void* const* d_in, const int* in_sizes, int n_in,
                              void* d_out, int out_size)
{
    const float* x    = (const float*)d_in[0];
    const float* skin = (const float*)d_in[1];
    float* out  = (float*)d_out;
    float* attn = out + (size_t)B_ * C_ * T_ * WH_;   // second output region

    dim3 g1(K1_CHUNKS, HALF_FRAMES);
    k_reduce_b01<<<g1, NTHREADS>>>(x, skin);

    k_mixed<<<NPROD_H + NCONS_H, NTHREADS>>>(x, skin, out, attn);

    dim3 g3(64, 2 * C_);
    k_apply_b23<<<g3, NTHREADS>>>(x, out, attn);
}

// round 13
// speedup vs baseline: 1.1290x; 1.1290x over previous
#include <cuda_runtime.h>
#include <float.h>

// Problem constants
#define B_   4
#define C_   64
#define T_   32
#define WH_  4096                  // W*H per frame
#define FRAME4_ (WH_ / 4)          // 1024 float4 per frame
#define FRAME2_ (WH_ / 2)          // 2048 float2 per frame
#define PLANE4_ ((T_ * WH_) / 4)   // 32768 float4 per (b,c) plane
#define PLANE2_ ((T_ * WH_) / 2)   // 65536 float2 per (b,c) plane
#define NBT_ (B_ * T_)             // 128 frames

#define K1_CHUNKS  8               // blocks per frame in pass 1 (float2 per thread)
#define K1_THREADS 256

// Scratch (device globals — no allocation)
__device__ float g_e[(size_t)NBT_ * WH_];          // unnormalized exp(fusion), 2MB
__device__ float g_part[NBT_ * K1_CHUNKS];         // per-chunk exp-sums

__device__ __forceinline__ float sigmoidf_(float v) {
    return 1.0f / (1.0f + __expf(-v));
}

// ---------------- Pass 1: channel reduce + exp, partial sums ----------------
// grid (8, 128) = 1024 blocks, 256 threads, ONE float2 per thread.
// 8192 warps (2x the float4 variants): occupancy is the measured binder for
// this kernel's bandwidth (R12: 256 blk -> 3.1 TB/s, 512 blk -> 4.5 TB/s).
__global__ __launch_bounds__(K1_THREADS) void reduce_exp_kernel(
    const float* __restrict__ x,
    const float* __restrict__ skin)
{
    const int chunk = blockIdx.x;              // 0..7
    const int bt    = blockIdx.y;              // 0..127
    const int b     = bt >> 5;
    const int t     = bt & 31;
    const int tid   = threadIdx.x;
    const int p2    = chunk * K1_THREADS + tid;      // 0..2047 float2 within frame

    const size_t base2 = ((size_t)(b * C_ * T_) + t) * FRAME2_ + p2;
    const float2* __restrict__ x2 = (const float2*)x;

    float2 s = make_float2(0.f, 0.f);
    float2 m = make_float2(-FLT_MAX, -FLT_MAX);

    #pragma unroll 8
    for (int c = 0; c < C_; c++) {
        const float2 v = x2[base2 + (size_t)c * PLANE2_];
        s.x += v.x; s.y += v.y;
        m.x = fmaxf(m.x, v.x); m.y = fmaxf(m.y, v.y);
    }

    const float2 k = __ldcs(&((const float2*)skin)[(size_t)bt * FRAME2_ + p2]);

    const float inv_c = 1.0f / (float)C_;
    float2 e;
    // fusion in (0,3): exp is safe without max subtraction
    e.x = __expf(sigmoidf_(s.x * inv_c) + sigmoidf_(m.x) + k.x);
    e.y = __expf(sigmoidf_(s.y * inv_c) + sigmoidf_(m.y) + k.y);

    ((float2*)g_e)[(size_t)bt * FRAME2_ + p2] = e;

    // block sum of e
    float ls = e.x + e.y;
    #pragma unroll
    for (int o = 16; o; o >>= 1) ls += __shfl_xor_sync(0xffffffffu, ls, o);

    __shared__ float red[8];
    if ((tid & 31) == 0) red[tid >> 5] = ls;
    __syncthreads();
    if (tid == 0) {
        float v = red[0];
        #pragma unroll
        for (int w = 1; w < 8; w++) v += red[w];
        g_part[bt * K1_CHUNKS + chunk] = v;
    }
}

// ---------------- Pass 2: out = x * e * inv_sum; c==0 planes write attn -------
// Identical to the best-measured (R6) apply kernel: reversed traversal to
// harvest pass-1's L2 tail, __ldcs last-use loads, __stcs evict-first stores.
__global__ __launch_bounds__(256) void apply_kernel(
    const float* __restrict__ x,
    float* __restrict__ out,
    float* __restrict__ attn)
{
    const int plane = (B_ * C_ - 1) - blockIdx.y;        // 255..0
    const int blk   = (gridDim.x - 1) - blockIdx.x;      // 63..0
    const int b     = plane >> 6;
    const int c     = plane & 63;
    const int i4    = blk * 512 + threadIdx.x;           // first float4 index
    const int t     = blk >> 1;                           // block-constant frame
    const int bt    = b * T_ + t;

    const size_t px = (size_t)plane * PLANE4_ + i4;
    const size_t pa = (size_t)b * PLANE4_ + i4;   // index into g_e / attn

    const float4 xv0 = __ldcs(&((const float4*)x)[px]);
    const float4 xv1 = __ldcs(&((const float4*)x)[px + 256]);
    const float4 ev0 = __ldcs(&((const float4*)g_e)[pa]);
    const float4 ev1 = __ldcs(&((const float4*)g_e)[pa + 256]);

    const float* __restrict__ p = &g_part[bt * K1_CHUNKS];
    float tot = 0.f;
    #pragma unroll
    for (int r = 0; r < K1_CHUNKS; r++) tot += p[r];
    const float inv = __frcp_rn(tot);

    float4 a0, a1;
    a0.x = ev0.x * inv; a0.y = ev0.y * inv; a0.z = ev0.z * inv; a0.w = ev0.w * inv;
    a1.x = ev1.x * inv; a1.y = ev1.y * inv; a1.z = ev1.z * inv; a1.w = ev1.w * inv;

    float4 o0, o1;
    o0.x = xv0.x * a0.x; o0.y = xv0.y * a0.y; o0.z = xv0.z * a0.z; o0.w = xv0.w * a0.w;
    o1.x = xv1.x * a1.x; o1.y = xv1.y * a1.y; o1.z = xv1.z * a1.z; o1.w = xv1.w * a1.w;

    __stcs(&((float4*)out)[px],       o0);
    __stcs(&((float4*)out)[px + 256], o1);

    if (c == 0) {
        __stcs(&((float4*)attn)[pa],       a0);
        __stcs(&((float4*)attn)[pa + 256], a1);
    }
}

extern "C" void kernel_launch(void* const* d_in, const int* in_sizes, int n_in,
                              void* d_out, int out_size)
{
    const float* x    = (const float*)d_in[0];
    const float* skin = (const float*)d_in[1];
    float* out  = (float*)d_out;
    float* attn = out + (size_t)B_ * C_ * T_ * WH_;   // second output region

    dim3 g1(K1_CHUNKS, NBT_);
    reduce_exp_kernel<<<g1, K1_THREADS>>>(x, skin);

    dim3 g2(PLANE4_ / 512, B_ * C_);
    apply_kernel<<<g2, 256>>>(x, out, attn);
}